// round 15
// baseline (speedup 1.0000x reference)
#include <cuda_runtime.h>
#include <cstdint>

// ---------------------------------------------------------------------------
// Shapes
// ---------------------------------------------------------------------------
#define BT   12
#define CF   1024
#define CQ   128
#define NTOK 2401
#define NP   2432
#define HF   49

// ---------------------------------------------------------------------------
// Scratch
// ---------------------------------------------------------------------------
__device__ float g_XT [(size_t)BT * NP * CF];   // raw XT (q/k path)
__device__ float g_XTh[(size_t)BT * NP * CF];   // tf32-rounded XT (v path)
__device__ float g_Wvh[(size_t)CF * CF];        // tf32-rounded Wv
__device__ float g_QT [(size_t)BT * NP * CQ];   // raw q
__device__ float g_KT [(size_t)BT * NP * CQ];   // raw k
__device__ float g_V  [(size_t)BT * CF * NP];   // tf32-rounded v (incl bias)
__device__ float g_ATT[(size_t)BT * NP * NP];   // raw scores -> tf32-rounded probs

__device__ __forceinline__ uint32_t f2tf(float f) {
    uint32_t u; asm("cvt.rna.tf32.f32 %0, %1;" : "=r"(u) : "f"(f)); return u;
}
__device__ __forceinline__ float tf32f(float f) { return __uint_as_float(f2tf(f)); }
__device__ __forceinline__ uint32_t u2tf(uint32_t x) {
    uint32_t u; asm("cvt.rna.tf32.f32 %0, %1;" : "=r"(u) : "f"(__uint_as_float(x))); return u;
}
__device__ __forceinline__ uint32_t smem_u32(const void* p) {
    uint32_t a;
    asm("{ .reg .u64 t; cvta.to.shared.u64 t, %1; cvt.u32.u64 %0, t; }" : "=r"(a) : "l"(p));
    return a;
}

// residual gather: x[bt][c][n] straight from inputs (L2-resident)
__device__ __forceinline__ float gather_x(const float* __restrict__ img,
                                          const float* __restrict__ tac,
                                          int bt, int c, int n) {
    int i = n / HF, j = n % HF;
    return (c < 512)
        ? tac[(((size_t)bt * 512 + c) * 7 + (i / 7)) * 7 + (j / 7)]
        : img[(((size_t)bt * 512 + (c - 512)) * 7 + (i % 7)) * 7 + (j % 7)];
}

__device__ __forceinline__ void mma_tf32(float c[4], const uint32_t a[4], const uint32_t b[2]) {
    asm volatile(
        "mma.sync.aligned.m16n8k8.row.col.f32.tf32.tf32.f32 "
        "{%0,%1,%2,%3}, {%4,%5,%6,%7}, {%8,%9}, {%0,%1,%2,%3};"
        : "+f"(c[0]), "+f"(c[1]), "+f"(c[2]), "+f"(c[3])
        : "r"(a[0]), "r"(a[1]), "r"(a[2]), "r"(a[3]), "r"(b[0]), "r"(b[1]));
}

#define CP_ASYNC16(dst_u32, src_ptr) \
    asm volatile("cp.async.cg.shared.global [%0], [%1], 16;" :: "r"(dst_u32), "l"(src_ptr) : "memory")
#define CP_COMMIT() asm volatile("cp.async.commit_group;" ::: "memory")
#define CP_WAIT0()  asm volatile("cp.async.wait_group 0;" ::: "memory")

// ---------------------------------------------------------------------------
// 1) XT raw + rounded (zero rows for n >= NTOK)
// ---------------------------------------------------------------------------
__global__ void build_xt_kernel(const float* __restrict__ img,
                                const float* __restrict__ tac) {
    int c = blockIdx.x * 256 + threadIdx.x;
    int n = blockIdx.y, bt = blockIdx.z;
    if (c >= CF) return;
    float v = 0.0f;
    if (n < NTOK) v = gather_x(img, tac, bt, c, n);
    size_t base = ((size_t)bt * NP + n) * CF + c;
    g_XT[base]  = v;
    g_XTh[base] = tf32f(v);
}

// ---------------------------------------------------------------------------
// 1b) Wv -> rounded
// ---------------------------------------------------------------------------
__global__ void prep_round_kernel(const float* __restrict__ src,
                                  float* __restrict__ dst, int n) {
    int i = blockIdx.x * 256 + threadIdx.x;
    if (i < n) dst[i] = tf32f(src[i]);
}

// ---------------------------------------------------------------------------
// 2) row softmax (m < 2401), writes tf32-rounded probs, zeroes padding
// ---------------------------------------------------------------------------
__global__ __launch_bounds__(256)
void softmax_kernel() {
    __shared__ float row[NTOK];
    __shared__ float red[256];
    const int n = blockIdx.x, bt = blockIdx.y;
    float* base = g_ATT + ((size_t)bt * NP + n) * NP;
    const int t = threadIdx.x;

    float mx = -1e30f;
    for (int m = t; m < NTOK; m += 256) { float v = base[m]; row[m] = v; mx = fmaxf(mx, v); }
    red[t] = mx; __syncthreads();
    for (int s = 128; s > 0; s >>= 1) { if (t < s) red[t] = fmaxf(red[t], red[t + s]); __syncthreads(); }
    mx = red[0]; __syncthreads();

    float sum = 0.0f;
    for (int m = t; m < NTOK; m += 256) { float e = __expf(row[m] - mx); row[m] = e; sum += e; }
    red[t] = sum; __syncthreads();
    for (int s = 128; s > 0; s >>= 1) { if (t < s) red[t] += red[t + s]; __syncthreads(); }
    float inv = 1.0f / red[0];

    for (int m = t; m < NTOK; m += 256) base[m] = tf32f(row[m] * inv);
    for (int m = NTOK + t; m < NP; m += 256) base[m] = 0.0f;
}

// ---------------------------------------------------------------------------
// Shared tiling constants (stride-36 layout, conflict-free scalar LDS)
// ---------------------------------------------------------------------------
#define LDS_S 36
#define TILEW (128 * LDS_S)            // words per 128x32 tile
#define SMEM_T (4 * TILEW * 4)         // 73728 B double buffer

// ---------------------------------------------------------------------------
// 3) SPLIT=1 GEMM on PRE-ROUNDED operands: pure LDS+MMA mainloop, ONE barrier
//    per chunk (wait -> barrier -> issue next -> compute).
//    C[M,N] = A[M,K] @ B[N,K]^T (both K-major). 256 thr (8 warps 2Mx4N,
//    warp tile 64x32), chunk 32, 2-stage cp.async, 2 CTAs/SM.
//    EPI 0: C = tf32f(acc + bias[row])                (v writeback)
//    EPI 1: C = gamma*acc + gather_x(row,col), col<NTOK  (final output)
// ---------------------------------------------------------------------------
template <int EPI>
__global__ __launch_bounds__(256, 2)
void gemm_async_kernel(const float* __restrict__ A, int lda, size_t strideA,
                       const float* __restrict__ B, int ldb, size_t strideB,
                       int K,
                       const float* __restrict__ bias,
                       const float* __restrict__ gamma,
                       const float* __restrict__ img,
                       const float* __restrict__ tac,
                       float* __restrict__ C, int ldc, size_t strideC) {
    extern __shared__ uint32_t sm[];
    const uint32_t smem_base = smem_u32(sm);

    const int bt = blockIdx.z;
    const int m0 = blockIdx.x * 128;
    const int n0 = blockIdx.y * 128;
    const float* Ab = A + (size_t)bt * strideA + (size_t)m0 * lda;
    const float* Bb = B + (size_t)bt * strideB + (size_t)n0 * ldb;

    const int t = threadIdx.x;
    const int wid = t >> 5, lane = t & 31;
    const int warp_m = wid & 1, warp_n = wid >> 1;
    const int l4 = lane >> 2, lm = lane & 3;

    const int prow = t >> 1;
    const int pcol = (t & 1) * 16;
    const float* aRow = Ab + (size_t)prow * lda + pcol;
    const float* bRow = Bb + (size_t)prow * ldb + pcol;
    const uint32_t sA0 = smem_base + (prow * LDS_S + pcol) * 4;
    const uint32_t sB0 = sA0 + TILEW * 4;

    float acc[4][4][4];
    #pragma unroll
    for (int mi = 0; mi < 4; mi++)
        #pragma unroll
        for (int ni = 0; ni < 4; ni++)
            #pragma unroll
            for (int r = 0; r < 4; r++) acc[mi][ni][r] = 0.0f;

    const int NCH = K / 32;

    // prologue: chunk 0 into buffer 0
    #pragma unroll
    for (int q = 0; q < 4; q++) {
        CP_ASYNC16(sA0 + q * 16, aRow + q * 4);
        CP_ASYNC16(sB0 + q * 16, bRow + q * 4);
    }
    CP_COMMIT();

    for (int ch = 0; ch < NCH; ch++) {
        const int buf = ch & 1;
        CP_WAIT0();
        __syncthreads();
        if (ch + 1 < NCH) {
            const int k1 = (ch + 1) * 32;
            const uint32_t dA = sA0 + (buf ^ 1) * (2 * TILEW * 4);
            const uint32_t dB = sB0 + (buf ^ 1) * (2 * TILEW * 4);
            #pragma unroll
            for (int q = 0; q < 4; q++) {
                CP_ASYNC16(dA + q * 16, aRow + k1 + q * 4);
                CP_ASYNC16(dB + q * 16, bRow + k1 + q * 4);
            }
            CP_COMMIT();
        }

        const uint32_t* as = sm + buf * 2 * TILEW;
        const uint32_t* bs = as + TILEW;
        #pragma unroll
        for (int g = 0; g < 4; g++) {
            const int kk = g * 8;
            uint32_t b[4][2];
            #pragma unroll
            for (int ni = 0; ni < 4; ni++) {
                const int base = (warp_n * 32 + ni * 8 + l4) * LDS_S + kk + lm;
                b[ni][0] = bs[base];
                b[ni][1] = bs[base + 4];
            }
            #pragma unroll
            for (int mi = 0; mi < 4; mi++) {
                const int base = (warp_m * 64 + mi * 16 + l4) * LDS_S + kk + lm;
                uint32_t a[4];
                a[0] = as[base];
                a[1] = as[base + 8 * LDS_S];
                a[2] = as[base + 4];
                a[3] = as[base + 8 * LDS_S + 4];
                #pragma unroll
                for (int ni = 0; ni < 4; ni++) mma_tf32(acc[mi][ni], a, b[ni]);
            }
        }
    }

    float* Cb = C + (size_t)bt * strideC;
    if (EPI == 0) {
        #pragma unroll
        for (int mi = 0; mi < 4; mi++) {
            const int gr = m0 + warp_m * 64 + mi * 16 + l4;
            const float bv0 = bias[gr], bv8 = bias[gr + 8];
            #pragma unroll
            for (int ni = 0; ni < 4; ni++) {
                const int gc = n0 + warp_n * 32 + ni * 8 + lm * 2;
                float2 o0 = { tf32f(acc[mi][ni][0] + bv0), tf32f(acc[mi][ni][1] + bv0) };
                float2 o1 = { tf32f(acc[mi][ni][2] + bv8), tf32f(acc[mi][ni][3] + bv8) };
                *reinterpret_cast<float2*>(&Cb[(size_t)gr * ldc + gc]) = o0;
                *reinterpret_cast<float2*>(&Cb[(size_t)(gr + 8) * ldc + gc]) = o1;
            }
        }
    } else {
        const float g = __ldg(gamma);
        #pragma unroll
        for (int mi = 0; mi < 4; mi++) {
            const int gr = m0 + warp_m * 64 + mi * 16 + l4;
            #pragma unroll
            for (int ni = 0; ni < 4; ni++) {
                const int gc = n0 + warp_n * 32 + ni * 8 + lm * 2;
                if (gc < NTOK)
                    Cb[(size_t)gr * ldc + gc] =
                        g * acc[mi][ni][0] + gather_x(img, tac, bt, gr, gc);
                if (gc + 1 < NTOK)
                    Cb[(size_t)gr * ldc + gc + 1] =
                        g * acc[mi][ni][1] + gather_x(img, tac, bt, gr, gc + 1);
                if (gc < NTOK)
                    Cb[(size_t)(gr + 8) * ldc + gc] =
                        g * acc[mi][ni][2] + gather_x(img, tac, bt, gr + 8, gc);
                if (gc + 1 < NTOK)
                    Cb[(size_t)(gr + 8) * ldc + gc + 1] =
                        g * acc[mi][ni][3] + gather_x(img, tac, bt, gr + 8, gc + 1);
            }
        }
    }
}

// ---------------------------------------------------------------------------
// 4) SPLIT=3 (3xTF32) GEMM: raw staging, hi/lo split on consume, chunk 32,
//    ONE barrier per chunk, 256 threads, 2 CTAs/SM.
//    EPI 2: fused q/k projection (blockIdx.y selects B/bias/C), C = acc + bias[col]
//    EPI 3: C = acc (raw scores)
// ---------------------------------------------------------------------------
template <int EPI>
__global__ __launch_bounds__(256, 2)
void gemm_async3_kernel(const float* __restrict__ A, int lda, size_t strideA,
                        const float* __restrict__ B, int ldb, size_t strideB,
                        const float* __restrict__ B2,
                        int K,
                        const float* __restrict__ bias,
                        const float* __restrict__ bias2,
                        float* __restrict__ C, int ldc, size_t strideC,
                        float* __restrict__ C2) {
    extern __shared__ uint32_t sm[];
    const uint32_t smem_base = smem_u32(sm);

    const int bt = blockIdx.z;
    const int m0 = blockIdx.x * 128;
    int n0;
    const float* Bsel;
    const float* biassel;
    float* Csel;
    if (EPI == 2) {
        n0 = 0;
        const bool alt = (blockIdx.y != 0);
        Bsel = alt ? B2 : B;
        biassel = alt ? bias2 : bias;
        Csel = alt ? C2 : C;
    } else {
        n0 = blockIdx.y * 128;
        Bsel = B; biassel = bias; Csel = C;
    }

    const float* Ab = A + (size_t)bt * strideA + (size_t)m0 * lda;
    const float* Bb = Bsel + (size_t)bt * strideB + (size_t)n0 * ldb;

    const int t = threadIdx.x;
    const int wid = t >> 5, lane = t & 31;
    const int warp_m = wid & 1, warp_n = wid >> 1;
    const int l4 = lane >> 2, lm = lane & 3;

    const int prow = t >> 1;
    const int pcol = (t & 1) * 16;
    const float* aRow = Ab + (size_t)prow * lda + pcol;
    const float* bRow = Bb + (size_t)prow * ldb + pcol;
    const uint32_t sA0 = smem_base + (prow * LDS_S + pcol) * 4;
    const uint32_t sB0 = sA0 + TILEW * 4;

    float acc[4][4][4];
    #pragma unroll
    for (int mi = 0; mi < 4; mi++)
        #pragma unroll
        for (int ni = 0; ni < 4; ni++)
            #pragma unroll
            for (int r = 0; r < 4; r++) acc[mi][ni][r] = 0.0f;

    const int NCH = K / 32;

    #pragma unroll
    for (int q = 0; q < 4; q++) {
        CP_ASYNC16(sA0 + q * 16, aRow + q * 4);
        CP_ASYNC16(sB0 + q * 16, bRow + q * 4);
    }
    CP_COMMIT();

    for (int ch = 0; ch < NCH; ch++) {
        const int buf = ch & 1;
        CP_WAIT0();
        __syncthreads();
        if (ch + 1 < NCH) {
            const int k1 = (ch + 1) * 32;
            const uint32_t dA = sA0 + (buf ^ 1) * (2 * TILEW * 4);
            const uint32_t dB = sB0 + (buf ^ 1) * (2 * TILEW * 4);
            #pragma unroll
            for (int q = 0; q < 4; q++) {
                CP_ASYNC16(dA + q * 16, aRow + k1 + q * 4);
                CP_ASYNC16(dB + q * 16, bRow + k1 + q * 4);
            }
            CP_COMMIT();
        }

        const uint32_t* as = sm + buf * 2 * TILEW;
        const uint32_t* bs = as + TILEW;
        #pragma unroll
        for (int g = 0; g < 4; g++) {
            const int kk = g * 8;
            uint32_t bh[4][2], bl[4][2];
            #pragma unroll
            for (int ni = 0; ni < 4; ni++) {
                const int base = (warp_n * 32 + ni * 8 + l4) * LDS_S + kk + lm;
                const uint32_t r0 = bs[base], r1 = bs[base + 4];
                bh[ni][0] = u2tf(r0);
                bl[ni][0] = f2tf(__uint_as_float(r0) - __uint_as_float(bh[ni][0]));
                bh[ni][1] = u2tf(r1);
                bl[ni][1] = f2tf(__uint_as_float(r1) - __uint_as_float(bh[ni][1]));
            }
            #pragma unroll
            for (int mi = 0; mi < 4; mi++) {
                const int base = (warp_m * 64 + mi * 16 + l4) * LDS_S + kk + lm;
                uint32_t ar[4];
                ar[0] = as[base];
                ar[1] = as[base + 8 * LDS_S];
                ar[2] = as[base + 4];
                ar[3] = as[base + 8 * LDS_S + 4];
                uint32_t ah[4], al[4];
                #pragma unroll
                for (int r = 0; r < 4; r++) {
                    ah[r] = u2tf(ar[r]);
                    al[r] = f2tf(__uint_as_float(ar[r]) - __uint_as_float(ah[r]));
                }
                #pragma unroll
                for (int ni = 0; ni < 4; ni++) {
                    mma_tf32(acc[mi][ni], ah, bl[ni]);
                    mma_tf32(acc[mi][ni], al, bh[ni]);
                    mma_tf32(acc[mi][ni], ah, bh[ni]);
                }
            }
        }
    }

    float* Cb = Csel + (size_t)bt * strideC;
    if (EPI == 2) {
        #pragma unroll
        for (int mi = 0; mi < 4; mi++) {
            const int gr = m0 + warp_m * 64 + mi * 16 + l4;
            #pragma unroll
            for (int ni = 0; ni < 4; ni++) {
                const int gc = n0 + warp_n * 32 + ni * 8 + lm * 2;
                const float b0 = biassel[gc], b1 = biassel[gc + 1];
                float2 o0 = { acc[mi][ni][0] + b0, acc[mi][ni][1] + b1 };
                float2 o1 = { acc[mi][ni][2] + b0, acc[mi][ni][3] + b1 };
                *reinterpret_cast<float2*>(&Cb[(size_t)gr * ldc + gc]) = o0;
                *reinterpret_cast<float2*>(&Cb[(size_t)(gr + 8) * ldc + gc]) = o1;
            }
        }
    } else {
        #pragma unroll
        for (int mi = 0; mi < 4; mi++) {
            const int gr = m0 + warp_m * 64 + mi * 16 + l4;
            #pragma unroll
            for (int ni = 0; ni < 4; ni++) {
                const int gc = n0 + warp_n * 32 + ni * 8 + lm * 2;
                float2 o0 = { acc[mi][ni][0], acc[mi][ni][1] };
                float2 o1 = { acc[mi][ni][2], acc[mi][ni][3] };
                *reinterpret_cast<float2*>(&Cb[(size_t)gr * ldc + gc]) = o0;
                *reinterpret_cast<float2*>(&Cb[(size_t)(gr + 8) * ldc + gc]) = o1;
            }
        }
    }
}

// ---------------------------------------------------------------------------
// Launch
// ---------------------------------------------------------------------------
extern "C" void kernel_launch(void* const* d_in, const int* in_sizes, int n_in,
                              void* d_out, int out_size) {
    const float* img   = (const float*)d_in[0];
    const float* tac   = (const float*)d_in[1];
    const float* Wq    = (const float*)d_in[2];
    const float* bq    = (const float*)d_in[3];
    const float* Wk    = (const float*)d_in[4];
    const float* bk    = (const float*)d_in[5];
    const float* Wv    = (const float*)d_in[6];
    const float* bv    = (const float*)d_in[7];
    const float* gamma = (const float*)d_in[8];
    float* out = (float*)d_out;

    float *gXT, *gXTh, *gWvh, *gQT, *gKT, *gV, *gA;
    cudaGetSymbolAddress((void**)&gXT,  g_XT);
    cudaGetSymbolAddress((void**)&gXTh, g_XTh);
    cudaGetSymbolAddress((void**)&gWvh, g_Wvh);
    cudaGetSymbolAddress((void**)&gQT,  g_QT);
    cudaGetSymbolAddress((void**)&gKT,  g_KT);
    cudaGetSymbolAddress((void**)&gV,   g_V);
    cudaGetSymbolAddress((void**)&gA,   g_ATT);

    cudaFuncSetAttribute(gemm_async_kernel<0>,  cudaFuncAttributeMaxDynamicSharedMemorySize, SMEM_T);
    cudaFuncSetAttribute(gemm_async_kernel<1>,  cudaFuncAttributeMaxDynamicSharedMemorySize, SMEM_T);
    cudaFuncSetAttribute(gemm_async3_kernel<2>, cudaFuncAttributeMaxDynamicSharedMemorySize, SMEM_T);
    cudaFuncSetAttribute(gemm_async3_kernel<3>, cudaFuncAttributeMaxDynamicSharedMemorySize, SMEM_T);

    // 1) XT (raw + rounded) + rounded Wv  (residual gathered in out epilogue)
    build_xt_kernel<<<dim3(CF / 256, NP, BT), 256>>>(img, tac);
    prep_round_kernel<<<(CF * CF + 255) / 256, 256>>>(Wv, gWvh, CF * CF);

    // 2) fused q+k projections (3xTF32, raw operands, split on consume)
    gemm_async3_kernel<2><<<dim3(NP / 128, 2, BT), 256, SMEM_T>>>(
        gXT, CF, (size_t)NP * CF,
        Wq, CF, 0, Wk,
        CF, bq, bk,
        gQT, CQ, (size_t)NP * CQ, gKT);

    // 3) v projection (pre-rounded operands, no cvt in mainloop)
    gemm_async_kernel<0><<<dim3(CF / 128, NP / 128, BT), 256, SMEM_T>>>(
        gWvh, CF, 0,
        gXTh, CF, (size_t)NP * CF,
        CF, bv, nullptr, nullptr, nullptr,
        gV, NP, (size_t)CF * NP);

    // 4) attention scores (3xTF32, raw q/k, split on consume)
    gemm_async3_kernel<3><<<dim3(NP / 128, NP / 128, BT), 256, SMEM_T>>>(
        gQT, CQ, (size_t)NP * CQ,
        gKT, CQ, (size_t)NP * CQ, nullptr,
        CQ, nullptr, nullptr,
        gA, NP, (size_t)NP * NP, nullptr);

    // 5) softmax -> tf32-rounded probs
    softmax_kernel<<<dim3(NTOK, BT), 256>>>();

    // 6) out = gamma * (V @ P^T) + gather_x (fused residual)
    gemm_async_kernel<1><<<dim3(CF / 128, NP / 128, BT), 256, SMEM_T>>>(
        gV, NP, (size_t)CF * NP,
        gA, NP, (size_t)NP * NP,
        NP, nullptr, gamma, img, tac,
        out, NTOK, (size_t)CF * NTOK);
}